// round 16
// baseline (speedup 1.0000x reference)
#include <cuda_runtime.h>
#include <math.h>

#define BATCH   16
#define NLOC    7581
#define NLOCP   7584
#define TOPK    4096
#define CAP2    262144
#define CAPB    6144
#define MAXDET  100
#define NBINS   8192
#define FBINS   4096
#define VECTOT  1896
#define U64MAX  0xFFFFFFFFFFFFFFFFull
#define KEYMAX  0xBF800000u
#define NEG_INF __int_as_float(0xff800000)

__device__ float              g_objs[BATCH * 3 * NLOCP];
__device__ float              g_thr [BATCH * 3 * NLOCP];
__device__ unsigned int       g_hist[BATCH * NBINS];
__device__ unsigned int       g_lbkey[BATCH];
__device__ int                g_shift[BATCH];
__device__ int                g_cnt[BATCH];
__device__ unsigned long long g_cand[(size_t)BATCH * CAP2];
__device__ unsigned long long g_comp[BATCH * TOPK];
__device__ float4             g_box [BATCH * TOPK];
__device__ int                g_clsidx[BATCH * TOPK];
__device__ int                g_coffs[BATCH * 81];
__device__ float              g_ob[BATCH];

__constant__ int   c_lb[3]  = {0, 361, 1805};
__constant__ int   c_lbp[3] = {0, 364, 1808};
__constant__ int   c_HW[3]  = {361, 1444, 5776};
__constant__ int   c_W[3]   = {19, 38, 76};
__constant__ int   c_nb[3]  = {0, 1083, 5415};
__constant__ float c_str[3] = {32.f, 16.f, 8.f};
__constant__ float c_bw2[9] = {58.f, 78.f, 186.5f,  15.f, 31.f, 29.5f,  5.f, 8.f, 16.5f};
__constant__ float c_bh2[9] = {45.f, 99.f, 163.f,   30.5f, 22.5f, 59.5f, 6.5f, 15.f, 11.5f};

__device__ __forceinline__ float sigm(float x) { return 1.f / (1.f + expf(-x)); }

__device__ __forceinline__ void vecmap(int vec, int& m, int& vbase, int& HW) {
    if (vec < 91)       { m = 0; vbase = 0;   HW = 361;  }
    else if (vec < 452) { m = 1; vbase = 91;  HW = 1444; }
    else                { m = 2; vbase = 452; HW = 5776; }
}

__device__ __forceinline__ void hadd(unsigned int* hist, int bin, bool active) {
    unsigned int amask = __ballot_sync(0xffffffffu, active);
    if (active) {
        unsigned int peers = __match_any_sync(amask, bin);
        int leader = __ffs(peers) - 1;
        if ((threadIdx.x & 31) == leader)
            atomicAdd(&hist[bin], (unsigned int)__popc(peers));
    }
}

// ---------------- fused objectness + per-anchor max-class histogram ----------------
__global__ __launch_bounds__(256) void amax_kernel(const float* __restrict__ m0,
                                                   const float* __restrict__ m1,
                                                   const float* __restrict__ m2) {
    __shared__ unsigned int sh[NBINS];
    int tid = threadIdx.x;
    for (int i = tid; i < NBINS; i += 256) sh[i] = 0u;
    __syncthreads();
    int b = blockIdx.z, a = blockIdx.y;
    int vec = blockIdx.x * 256 + tid;
    if (vec < VECTOT) {
        int m, vbase, HW; vecmap(vec, m, vbase, HW);
        int locm = (vec - vbase) * 4;
        int nv = HW - locm; if (nv > 4) nv = 4;
        const float* mp = (m == 0) ? m0 : ((m == 1) ? m1 : m2);
        const float* ch0 = mp + ((size_t)(b * 255 + a * 85)) * (size_t)HW;
        float cm0 = -1e30f, cm1 = -1e30f, cm2 = -1e30f, cm3 = -1e30f;
        float o0 = 0.f, o1 = 0.f, o2 = 0.f, o3 = 0.f;
        if (m > 0) {
            const float* cls = ch0 + (size_t)5 * HW + locm;
#pragma unroll 10
            for (int ch = 0; ch < 80; ++ch) {
                float4 v = __ldg((const float4*)(cls + (size_t)ch * HW));
                cm0 = fmaxf(cm0, v.x); cm1 = fmaxf(cm1, v.y);
                cm2 = fmaxf(cm2, v.z); cm3 = fmaxf(cm3, v.w);
            }
            float4 ov = __ldg((const float4*)(ch0 + (size_t)4 * HW + locm));
            o0 = ov.x; o1 = ov.y; o2 = ov.z; o3 = ov.w;
        } else {
            const float* cls = ch0 + (size_t)5 * HW + locm;
            for (int ch = 0; ch < 80; ++ch) {
                const float* r = cls + (size_t)ch * HW;
                cm0 = fmaxf(cm0, r[0]);
                if (nv > 1) cm1 = fmaxf(cm1, r[1]);
                if (nv > 2) cm2 = fmaxf(cm2, r[2]);
                if (nv > 3) cm3 = fmaxf(cm3, r[3]);
            }
            const float* orow = ch0 + (size_t)4 * HW + locm;
            o0 = orow[0];
            if (nv > 1) o1 = orow[1];
            if (nv > 2) o2 = orow[2];
            if (nv > 3) o3 = orow[3];
        }
        float cmv[4] = {cm0, cm1, cm2, cm3};
        float tov[4] = {o0, o1, o2, o3};
        int obase = (b * 3 + a) * NLOCP + c_lbp[m] + locm;
#pragma unroll
        for (int e = 0; e < 4; e++) {
            if (e < nv) {
                float obj = sigm(tov[e]);
                g_objs[obase + e] = obj;
                float cs = sigm(cmv[e]);
                unsigned int key = (obj >= 0.005f && cs > 0.05f)
                                       ? (__float_as_uint(cs * obj) | 0x80000000u) : 0u;
                atomicAdd(&sh[key >> 19], 1u);
            }
        }
    }
    __syncthreads();
    for (int i = tid; i < NBINS; i += 256) {
        unsigned int v = sh[i];
        if (v) atomicAdd(&g_hist[b * NBINS + i], v);
    }
}

// ---- top-down bin finders (1024 thr) ----
__device__ __forceinline__ void find_bin8(const unsigned int* hist, int K,
                                          int* part, int* wsum,
                                          int* out_bin, int* out_above) {
    int tid = threadIdx.x;
    int s = 0;
#pragma unroll
    for (int k = 0; k < 8; k++) s += (int)hist[tid * 8 + k];
    part[tid] = s;
    int v = s;
    for (int o = 16; o; o >>= 1) v += __shfl_xor_sync(0xffffffffu, v, o);
    if ((tid & 31) == 0) wsum[tid >> 5] = v;
    __syncthreads();
    if (tid == 0) {
        int cum = 0, bin = 0, wi;
        for (wi = 31; wi >= 0; --wi) {
            if (cum + wsum[wi] >= K) break;
            cum += wsum[wi];
        }
        if (wi >= 0) {
            int p;
            for (p = wi * 32 + 31; p > wi * 32; --p) {
                if (cum + part[p] >= K) break;
                cum += part[p];
            }
            int bb;
            for (bb = p * 8 + 7; bb > p * 8; --bb) {
                if (cum + (int)hist[bb] >= K) break;
                cum += (int)hist[bb];
            }
            bin = bb;
        }
        *out_bin = bin; *out_above = cum;
    }
    __syncthreads();
}

__device__ __forceinline__ void find_bin4(const unsigned int* hist, int K,
                                          int* part, int* wsum,
                                          int* out_bin, int* out_above) {
    int tid = threadIdx.x;
    int s = 0;
#pragma unroll
    for (int k = 0; k < 4; k++) s += (int)hist[tid * 4 + k];
    part[tid] = s;
    int v = s;
    for (int o = 16; o; o >>= 1) v += __shfl_xor_sync(0xffffffffu, v, o);
    if ((tid & 31) == 0) wsum[tid >> 5] = v;
    __syncthreads();
    if (tid == 0) {
        int cum = 0, bin = 0, wi;
        for (wi = 31; wi >= 0; --wi) {
            if (cum + wsum[wi] >= K) break;
            cum += wsum[wi];
        }
        if (wi >= 0) {
            int p;
            for (p = wi * 32 + 31; p > wi * 32; --p) {
                if (cum + part[p] >= K) break;
                cum += part[p];
            }
            int bb;
            for (bb = p * 4 + 3; bb > p * 4; --bb) {
                if (cum + (int)hist[bb] >= K) break;
                cum += (int)hist[bb];
            }
            bin = bb;
        }
        *out_bin = bin; *out_above = cum;
    }
    __syncthreads();
}

__device__ __forceinline__ void sel2048(const unsigned int* hist, int K, int top,
                                        int* part, int* wsum,
                                        int* out_bin, int* out_side) {
    int tid = threadIdx.x;
    int s = (int)hist[2 * tid] + (int)hist[2 * tid + 1];
    part[tid] = s;
    int v = s;
    for (int o = 16; o; o >>= 1) v += __shfl_xor_sync(0xffffffffu, v, o);
    if ((tid & 31) == 0) wsum[tid >> 5] = v;
    __syncthreads();
    if (tid == 0) {
        int cum = 0, bin;
        if (top) {
            int wi;
            for (wi = 31; wi > 0; --wi) {
                if (cum + wsum[wi] >= K) break;
                cum += wsum[wi];
            }
            int p;
            for (p = wi * 32 + 31; p > wi * 32; --p) {
                if (cum + part[p] >= K) break;
                cum += part[p];
            }
            int bb;
            for (bb = 2 * p + 1; bb > 2 * p; --bb) {
                if (cum + (int)hist[bb] >= K) break;
                cum += (int)hist[bb];
            }
            bin = bb;
        } else {
            int wi;
            for (wi = 0; wi < 31; ++wi) {
                if (cum + wsum[wi] >= K) break;
                cum += wsum[wi];
            }
            int p;
            for (p = wi * 32; p < wi * 32 + 31; ++p) {
                if (cum + part[p] >= K) break;
                cum += part[p];
            }
            int bb;
            for (bb = 2 * p; bb < 2 * p + 1; ++bb) {
                if (cum + (int)hist[bb] >= K) break;
                cum += (int)hist[bb];
            }
            bin = bb;
        }
        *out_bin = bin; *out_side = cum;
    }
    __syncthreads();
}

// ---------------- LB + fine shift (narrow) ----------------
__global__ __launch_bounds__(1024) void thr_kernel() {
    __shared__ unsigned int h[NBINS];
    __shared__ int part[1024];
    __shared__ int wsum[32];
    __shared__ int sbin, sabove;
    int b = blockIdx.x, tid = threadIdx.x;
    for (int i = tid; i < NBINS; i += 1024) {
        h[i] = g_hist[b * NBINS + i];
        g_hist[b * NBINS + i] = 0u;
    }
    __syncthreads();
    find_bin8(h, TOPK, part, wsum, &sbin, &sabove);
    if (tid == 0) {
        unsigned int lbkey = ((unsigned int)sbin) << 19;
        g_lbkey[b] = lbkey;
        unsigned int R = KEYMAX - lbkey;
        int sh = 0;
        while ((R >> sh) > (unsigned)(FBINS - 1)) sh++;
        g_shift[b] = sh;
    }
}

// ---------------- per-anchor raw-logit thresholds (wide) ----------------
__global__ __launch_bounds__(512) void thrw_kernel() {
    int t = blockIdx.x * 512 + threadIdx.x;
    if (t >= BATCH * 3 * NLOCP) return;
    int b = t / (3 * NLOCP);
    float LB = __uint_as_float(g_lbkey[b] & 0x7FFFFFFFu);
    float obj = g_objs[t];
    float thr;
    if (obj < 0.005f) thr = 3.0e38f;
    else if (LB <= 0.f) thr = -2.9446f;
    else {
        float ratio = LB / obj;
        if (ratio >= 1.0f) thr = 3.0e38f;
        else thr = fmaxf(logf(ratio / (1.0f - ratio)) - 1e-2f, -2.9446f);
    }
    g_thr[t] = thr;
}

// ------- candidate generation: anchor-major, one location/thread, 80-class loop -------
__global__ __launch_bounds__(512) void cand_kernel(const float* __restrict__ m0,
                                                   const float* __restrict__ m1,
                                                   const float* __restrict__ m2) {
    extern __shared__ char cms[];
    unsigned long long* sbuf = (unsigned long long*)cms;          // 48 KB [6144]
    unsigned int* shist = (unsigned int*)(cms + 49152);           // 16 KB [4096]
    __shared__ int scnt;
    __shared__ int sbase;
    int b = blockIdx.z, a = blockIdx.y;
    int tid = threadIdx.x;
    if (tid == 0) scnt = 0;
    for (int i = tid; i < FBINS; i += 512) shist[i] = 0u;
    __syncthreads();
    unsigned int lbk = g_lbkey[b];
    int shiftv = g_shift[b];

    int locg = blockIdx.x * 512 + tid;
    bool act = (locg < NLOC);
    size_t HW = 361;
    const float* base = m0;
    float thr = 3.0e38f, obj = 0.f;
    unsigned int idx0 = 0u;
    if (act) {
        int m = (locg < 361) ? 0 : ((locg < 1805) ? 1 : 2);
        int locm = locg - c_lb[m];
        HW = (size_t)c_HW[m];
        const float* mp = (m == 0) ? m0 : ((m == 1) ? m1 : m2);
        base = mp + ((size_t)(b * 255 + a * 85 + 5)) * HW + locm;
        int pidx = (b * 3 + a) * NLOCP + c_lbp[m] + locm;
        thr = g_thr[pidx];
        obj = g_objs[pidx];
        idx0 = (unsigned int)(c_nb[m] + locm * 3 + a) * 80u;
    }

    for (int ch = 0; ch < 80; ++ch) {
        if (act) {
            float c = __ldg(base + (size_t)ch * HW);
            if (c >= thr) {
                float cs = sigm(c);
                if (cs > 0.05f && obj >= 0.005f) {
                    unsigned int key = __float_as_uint(cs * obj) | 0x80000000u;
                    if (key >= lbk) {
                        int p = atomicAdd(&scnt, 1);
                        sbuf[p] = (((unsigned long long)(~key)) << 32)
                                  | (unsigned long long)(idx0 + (unsigned int)ch);
                        atomicAdd(&shist[(key - lbk) >> shiftv], 1u);
                    }
                }
            }
        }
        if ((ch & 3) == 3) {                  // every 4 channels: max growth 2048
            __syncthreads();
            if (scnt > CAPB - 2048) {
                int c2 = scnt;
                if (tid == 0) sbase = atomicAdd(&g_cnt[b], c2);
                __syncthreads();
                int gb = sbase;
                for (int i = tid; i < c2; i += 512) {
                    int pos = gb + i;
                    if (pos < CAP2) g_cand[(size_t)b * CAP2 + pos] = sbuf[i];
                }
                __syncthreads();
                if (tid == 0) scnt = 0;
            }
            __syncthreads();
        }
    }
    __syncthreads();
    int c2 = scnt;
    if (c2 > 0) {
        if (tid == 0) sbase = atomicAdd(&g_cnt[b], c2);
        __syncthreads();
        int gb = sbase;
        for (int i = tid; i < c2; i += 512) {
            int pos = gb + i;
            if (pos < CAP2) g_cand[(size_t)b * CAP2 + pos] = sbuf[i];
        }
    }
    for (int i = tid; i < FBINS; i += 512) {
        unsigned int v = shist[i];
        if (v) atomicAdd(&g_hist[b * NBINS + i], v);
    }
}

// ------- select: fine T2 + filtered load + exact cascade + decode + segmentation -------
__global__ __launch_bounds__(1024) void select_kernel(const float* __restrict__ m0,
                                                      const float* __restrict__ m1,
                                                      const float* __restrict__ m2) {
    extern __shared__ char smraw[];
    unsigned long long* comp2 = (unsigned long long*)smraw;          // 64 KB [8192]
    unsigned long long* comp = (unsigned long long*)(smraw + 65536); // 32 KB [4096]
    unsigned int* fineh = (unsigned int*)smraw;                      // overlaps comp2
    __shared__ unsigned int hist[2048];
    __shared__ int part[1024];
    __shared__ int wsum[32];
    __shared__ int sn, sb1, sa1, sb2, sa2, sb3, sa3, scnteq, sib1, sbl1, sib2, sdum;
    __shared__ int sfbin, sfdum;
    __shared__ int scc, scc2;
    __shared__ float wred[32];
    __shared__ int ccount[80];
    __shared__ int coffs[81];
    __shared__ int ccur[80];

    int b = blockIdx.x, tid = threadIdx.x;
    if (tid == 0) {
        int nn = g_cnt[b]; if (nn > CAP2) nn = CAP2;
        sn = nn; g_cnt[b] = 0;
        scc = 0;
    }
    if (tid < 80) { ccount[tid] = 0; ccur[tid] = 0; }
    __syncthreads();
    int n = sn;
    const unsigned long long* cand = g_cand + (size_t)b * CAP2;

    for (int i = tid; i < FBINS; i += 1024) {
        fineh[i] = g_hist[b * NBINS + i];
        g_hist[b * NBINS + i] = 0u;
    }
    __syncthreads();
    find_bin4(fineh, TOPK, part, wsum, &sfbin, &sfdum);
    unsigned int T2 = g_lbkey[b] + (((unsigned int)sfbin) << g_shift[b]);
    __syncthreads();

    for (int i = tid; i < n; i += 1024) {
        unsigned long long e = cand[i];
        unsigned int key = ~(unsigned int)(e >> 32);
        if (key >= T2) {
            int p = atomicAdd(&scc, 1);
            if (p < 8192) comp2[p] = e;
        }
    }
    __syncthreads();
    int m = scc; if (m > 8192) m = 8192;

    unsigned int T = 0u; int tie_sel = 0; unsigned int Istar = 0u;
    if (m > TOPK) {
        for (int i = tid; i < 2048; i += 1024) hist[i] = 0u;
        __syncthreads();
        for (int i = tid; i < m; i += 1024) {
            unsigned int key = ~(unsigned int)(comp2[i] >> 32);
            atomicAdd(&hist[key >> 21], 1u);
        }
        __syncthreads();
        sel2048(hist, TOPK, 1, part, wsum, &sb1, &sa1);
        int b1 = sb1, K2 = TOPK - sa1;
        __syncthreads();
        for (int i = tid; i < 2048; i += 1024) hist[i] = 0u;
        __syncthreads();
        for (int i = tid; i < m; i += 1024) {
            unsigned int key = ~(unsigned int)(comp2[i] >> 32);
            if ((int)(key >> 21) == b1) atomicAdd(&hist[(key >> 10) & 0x7FFu], 1u);
        }
        __syncthreads();
        sel2048(hist, K2, 1, part, wsum, &sb2, &sa2);
        int b2 = sb2, K3 = K2 - sa2;
        unsigned int pre = ((unsigned int)b1 << 11) | (unsigned int)b2;
        __syncthreads();
        for (int i = tid; i < 2048; i += 1024) hist[i] = 0u;
        __syncthreads();
        for (int i = tid; i < m; i += 1024) {
            unsigned int key = ~(unsigned int)(comp2[i] >> 32);
            if ((key >> 10) == pre) atomicAdd(&hist[key & 0x3FFu], 1u);
        }
        __syncthreads();
        sel2048(hist, K3, 1, part, wsum, &sb3, &sa3);
        if (tid == 0) scnteq = (int)hist[sb3];
        __syncthreads();
        T = (pre << 10) | (unsigned int)sb3;
        int need_eq = K3 - sa3;
        if (scnteq > need_eq) {
            tie_sel = 1;
            __syncthreads();
            for (int i = tid; i < 2048; i += 1024) hist[i] = 0u;
            __syncthreads();
            for (int i = tid; i < m; i += 1024) {
                unsigned long long e = comp2[i];
                unsigned int key = ~(unsigned int)(e >> 32);
                if (key == T) atomicAdd(&hist[((unsigned int)e) >> 11], 1u);
            }
            __syncthreads();
            sel2048(hist, need_eq, 0, part, wsum, &sib1, &sbl1);
            int ib1 = sib1, Kr = need_eq - sbl1;
            __syncthreads();
            for (int i = tid; i < 2048; i += 1024) hist[i] = 0u;
            __syncthreads();
            for (int i = tid; i < m; i += 1024) {
                unsigned long long e = comp2[i];
                unsigned int key = ~(unsigned int)(e >> 32);
                unsigned int idx = (unsigned int)e;
                if (key == T && (int)(idx >> 11) == ib1)
                    atomicAdd(&hist[idx & 0x7FFu], 1u);
            }
            __syncthreads();
            sel2048(hist, Kr, 0, part, wsum, &sib2, &sdum);
            Istar = (((unsigned int)sib1) << 11) | (unsigned int)sib2;
        }
    }
    if (tid == 0) scc2 = 0;
    __syncthreads();

    float lmax = NEG_INF;
    for (int i = tid; i < m; i += 1024) {
        unsigned long long e = comp2[i];
        unsigned int key = ~(unsigned int)(e >> 32);
        unsigned int idx = (unsigned int)e;
        bool keep;
        if (m <= TOPK) keep = true;
        else keep = (key > T) || (key == T && (!tie_sel || idx <= Istar));
        if (keep) {
            int slot = atomicAdd(&scc2, 1);
            int nI = (int)(idx / 80u);
            int mm = (nI < 1083) ? 0 : ((nI < 5415) ? 1 : 2);
            int rem = nI - c_nb[mm];
            int locm = rem / 3, a = rem - locm * 3;
            const float* mp = (mm == 0) ? m0 : ((mm == 1) ? m1 : m2);
            size_t HW = (size_t)c_HW[mm];
            const float* bp = mp + ((size_t)b * 255 + a * 85) * HW + locm;
            float tx = bp[0], ty = bp[HW], tw = bp[2 * HW], th = bp[3 * HW];
            float s = c_str[mm]; int W = c_W[mm];
            int hh = locm / W, ww = locm - hh * W;
            float sx = sigm(tx), sy = sigm(ty);
            float cx = (float)ww * s + 0.5f * s + (sx - 0.5f) * s;
            float cy = (float)hh * s + 0.5f * s + (sy - 0.5f) * s;
            float wx = c_bw2[mm * 3 + a] * expf(tw);
            float wy = c_bh2[mm * 3 + a] * expf(th);
            float4 bx = make_float4(cx - wx, cy - wy, cx + wx, cy + wy);
            comp[slot] = e;
            g_comp[b * TOPK + slot] = e;
            g_box[b * TOPK + slot] = bx;
            lmax = fmaxf(lmax, fmaxf(fmaxf(bx.x, bx.y), fmaxf(bx.z, bx.w)));
        }
    }
    __syncthreads();
    int kept = scc2;
    for (int i = tid; i < TOPK; i += 1024) {
        if (i >= kept) { comp[i] = U64MAX; g_comp[b * TOPK + i] = U64MAX; }
    }
    lmax = fmaxf(lmax, 0.f);
    for (int o = 16; o; o >>= 1) lmax = fmaxf(lmax, __shfl_xor_sync(0xffffffffu, lmax, o));
    if ((tid & 31) == 0) wred[tid >> 5] = lmax;
    __syncthreads();
    if (tid < 32) {
        float v = wred[tid];
        for (int o = 16; o; o >>= 1) v = fmaxf(v, __shfl_xor_sync(0xffffffffu, v, o));
        if (tid == 0) g_ob[b] = v + 1.0f;
    }
    __syncthreads();

    for (int i = tid; i < TOPK; i += 1024) {
        unsigned long long e = comp[i];
        if (e != U64MAX) atomicAdd((unsigned int*)&ccount[(unsigned int)e % 80u], 1u);
    }
    __syncthreads();
    if (tid == 0) {
        int acc = 0;
        for (int c = 0; c < 80; c++) { coffs[c] = acc; acc += ccount[c]; }
        coffs[80] = acc;
    }
    __syncthreads();
    if (tid < 81) g_coffs[b * 81 + tid] = coffs[tid];
    for (int i = tid; i < TOPK; i += 1024) {
        unsigned long long e = comp[i];
        if (e != U64MAX) {
            int lbl = (int)((unsigned int)e % 80u);
            int p = coffs[lbl] + atomicAdd(&ccur[lbl], 1);
            g_clsidx[b * TOPK + p] = i;
        }
    }
}

// ------- per-class greedy NMS: one warp-block per (class, image), 24 KB smem -------
__global__ __launch_bounds__(32) void nms_kernel() {
    extern __shared__ char nsm[];
    unsigned long long* lcomp = (unsigned long long*)nsm;       // 2 KB [256]
    float4* lbox = (float4*)(nsm + 2048);                       // 4 KB [256]
    int* gslot = (int*)(nsm + 6144);                            // 1 KB [256]
    int* lidx = (int*)(nsm + 7168);                             // 16 KB [4096]

    int c = blockIdx.x, b = blockIdx.y;
    int lane = threadIdx.x;
    int s0 = g_coffs[b * 81 + c], e0 = g_coffs[b * 81 + c + 1];
    int k = e0 - s0;
    if (k <= 1) return;
    float oc = (float)c * g_ob[b];

    if (k <= 256) {
        for (int i = lane; i < k; i += 32) {
            int g = g_clsidx[b * TOPK + s0 + i];
            gslot[i] = g;
            lcomp[i] = g_comp[b * TOPK + g];
            lbox[i] = g_box[b * TOPK + g];
            lidx[i] = i;
        }
        __syncwarp();
        for (int pos = 0; pos < k; ++pos) {
            unsigned long long best = U64MAX; int bi = pos;
            for (int i = pos + lane; i < k; i += 32) {
                unsigned long long v = lcomp[lidx[i]];
                if (v < best) { best = v; bi = i; }
            }
            for (int o = 16; o; o >>= 1) {
                unsigned long long ov = __shfl_xor_sync(0xffffffffu, best, o);
                int oi = __shfl_xor_sync(0xffffffffu, bi, o);
                if (ov < best) { best = ov; bi = oi; }
            }
            if (lane == 0 && bi != pos) {
                int t = lidx[pos]; lidx[pos] = lidx[bi]; lidx[bi] = t;
            }
            __syncwarp();
            int slot = lidx[pos];
            float4 bc = lbox[slot];
            float cx0 = bc.x + oc, cy0 = bc.y + oc, cx1 = bc.z + oc, cy1 = bc.w + oc;
            float a2 = (cx1 - cx0) * (cy1 - cy0);
            bool sup = false;
            for (int j = lane; j < pos; j += 32) {
                int sj = lidx[j];
                if (lcomp[sj] != U64MAX) {
                    float4 bk = lbox[sj];
                    float kx0 = bk.x + oc, ky0 = bk.y + oc;
                    float kx1 = bk.z + oc, ky1 = bk.w + oc;
                    float tlx = fmaxf(kx0, cx0), tly = fmaxf(ky0, cy0);
                    float brx = fminf(kx1, cx1), bry = fminf(ky1, cy1);
                    float iw = fmaxf(brx - tlx, 0.f), ih = fmaxf(bry - tly, 0.f);
                    float inter = iw * ih;
                    float a1 = (kx1 - kx0) * (ky1 - ky0);
                    if (inter / (a1 + a2 - inter + 1e-12f) > 0.45f) sup = true;
                }
            }
            if (__any_sync(0xffffffffu, sup)) {
                if (lane == 0) lcomp[slot] = U64MAX;
            }
            __syncwarp();
        }
        for (int i = lane; i < k; i += 32)
            g_comp[b * TOPK + gslot[i]] = lcomp[i];
    } else {
        for (int i = lane; i < k; i += 32) lidx[i] = g_clsidx[b * TOPK + s0 + i];
        __syncwarp();
        for (int pos = 0; pos < k; ++pos) {
            unsigned long long best = U64MAX; int bi = pos;
            for (int i = pos + lane; i < k; i += 32) {
                unsigned long long v = g_comp[b * TOPK + lidx[i]];
                if (v < best) { best = v; bi = i; }
            }
            for (int o = 16; o; o >>= 1) {
                unsigned long long ov = __shfl_xor_sync(0xffffffffu, best, o);
                int oi = __shfl_xor_sync(0xffffffffu, bi, o);
                if (ov < best) { best = ov; bi = oi; }
            }
            if (lane == 0 && bi != pos) {
                int t = lidx[pos]; lidx[pos] = lidx[bi]; lidx[bi] = t;
            }
            __syncwarp();
            int slot = lidx[pos];
            float4 bc = g_box[b * TOPK + slot];
            float cx0 = bc.x + oc, cy0 = bc.y + oc, cx1 = bc.z + oc, cy1 = bc.w + oc;
            float a2 = (cx1 - cx0) * (cy1 - cy0);
            bool sup = false;
            for (int j = lane; j < pos; j += 32) {
                int sj = lidx[j];
                if (g_comp[b * TOPK + sj] != U64MAX) {
                    float4 bk = g_box[b * TOPK + sj];
                    float kx0 = bk.x + oc, ky0 = bk.y + oc;
                    float kx1 = bk.z + oc, ky1 = bk.w + oc;
                    float tlx = fmaxf(kx0, cx0), tly = fmaxf(ky0, cy0);
                    float brx = fminf(kx1, cx1), bry = fminf(ky1, cy1);
                    float iw = fmaxf(brx - tlx, 0.f), ih = fmaxf(bry - tly, 0.f);
                    float inter = iw * ih;
                    float a1 = (kx1 - kx0) * (ky1 - ky0);
                    if (inter / (a1 + a2 - inter + 1e-12f) > 0.45f) sup = true;
                }
            }
            if (__any_sync(0xffffffffu, sup)) {
                if (lane == 0) g_comp[b * TOPK + slot] = U64MAX;
            }
            __syncwarp();
        }
    }
}

// ------- merge: top-100 survivors by composite order -------
__global__ __launch_bounds__(1024) void merge_kernel(float* __restrict__ out, int out_size) {
    extern __shared__ char msm[];
    unsigned long long* comp = (unsigned long long*)msm;        // 32 KB [4096]
    __shared__ unsigned int hist[2048];
    __shared__ int part[1024];
    __shared__ int wsum[32];
    __shared__ int snsurv, souta;
    __shared__ int ssbin, ssbelow;
    __shared__ unsigned long long outc[128];
    __shared__ int outslot[128];

    int b = blockIdx.x, tid = threadIdx.x;
    int lane = tid & 31;
    if (tid == 0) { snsurv = 0; souta = 0; }
    __syncthreads();
    {
        int lc = 0;
#pragma unroll
        for (int k2 = 0; k2 < 4; k2++) {
            int i = k2 * 1024 + tid;
            unsigned long long v = g_comp[b * TOPK + i];
            comp[i] = v;
            if (v != U64MAX) lc++;
        }
        for (int o = 16; o; o >>= 1) lc += __shfl_xor_sync(0xffffffffu, lc, o);
        if (lane == 0 && lc) atomicAdd(&snsurv, lc);
    }
    __syncthreads();
    int nsurv = snsurv;
    unsigned long long Cstar = U64MAX;
    if (nsurv > MAXDET) {
        unsigned long long pref = 0ull; int prefbits = 0; int K = MAXDET;
        const int shifts[6]  = {53, 42, 31, 20, 9, 0};
        const int bitsarr[6] = {11, 11, 11, 11, 11, 9};
        for (int p = 0; p < 6; p++) {
            for (int i = tid; i < 2048; i += 1024) hist[i] = 0u;
            __syncthreads();
            unsigned long long msk = (1ull << bitsarr[p]) - 1ull;
#pragma unroll
            for (int k2 = 0; k2 < 4; k2++) {
                int i = k2 * 1024 + tid;
                unsigned long long v = comp[i];
                bool act = (v != U64MAX) &&
                           (prefbits == 0 || (v >> (64 - prefbits)) == pref);
                hadd(hist, act ? (int)((v >> shifts[p]) & msk) : 0, act);
            }
            __syncthreads();
            sel2048(hist, K, 0, part, wsum, &ssbin, &ssbelow);
            pref = (pref << bitsarr[p]) | (unsigned long long)ssbin;
            prefbits += bitsarr[p];
            K -= ssbelow;
            __syncthreads();
        }
        Cstar = pref;
    }
#pragma unroll
    for (int k2 = 0; k2 < 4; k2++) {
        int i = k2 * 1024 + tid;
        unsigned long long v = comp[i];
        if (v != U64MAX && v <= Cstar) {
            int p = atomicAdd(&souta, 1);
            if (p < 128) { outc[p] = v; outslot[p] = i; }
        }
    }
    __syncthreads();
    int nout = souta; if (nout > 128) nout = 128;
    if (tid < 128 && tid >= nout) { outc[tid] = U64MAX; outslot[tid] = 0; }
    __syncthreads();
    for (int k = 2; k <= 128; k <<= 1) {
        for (int j = k >> 1; j > 0; j >>= 1) {
            if (tid < 128) {
                int ix = tid ^ j;
                if (ix > tid) {
                    unsigned long long A = outc[tid], B = outc[ix];
                    bool up = ((tid & k) == 0);
                    if ((A > B) == up) {
                        outc[tid] = B; outc[ix] = A;
                        int t = outslot[tid]; outslot[tid] = outslot[ix]; outslot[ix] = t;
                    }
                }
            }
            __syncthreads();
        }
    }
    bool dets_only = (out_size <= BATCH * MAXDET * 5);
    if (tid < MAXDET) {
        unsigned long long e = outc[tid];
        float* o = out + (size_t)(b * MAXDET + tid) * 5;
        if (e != U64MAX) {
            float4 bx = g_box[b * TOPK + outslot[tid]];
            unsigned int key = ~(unsigned int)(e >> 32);
            o[0] = bx.x; o[1] = bx.y; o[2] = bx.z; o[3] = bx.w;
            o[4] = __uint_as_float(key & 0x7FFFFFFFu);
            if (!dets_only)
                out[BATCH * MAXDET * 5 + b * MAXDET + tid] =
                    (float)((unsigned int)e % 80u);
        } else {
            o[0] = 0.f; o[1] = 0.f; o[2] = 0.f; o[3] = 0.f; o[4] = 0.f;
            if (!dets_only) out[BATCH * MAXDET * 5 + b * MAXDET + tid] = -1.0f;
        }
    }
}

// ---------------- launcher ----------------
extern "C" void kernel_launch(void* const* d_in, const int* in_sizes, int n_in,
                              void* d_out, int out_size) {
    const float* m0 = (const float*)d_in[0];
    const float* m1 = (const float*)d_in[1];
    const float* m2 = (const float*)d_in[2];
    float* out = (float*)d_out;

    cudaFuncSetAttribute(cand_kernel,   cudaFuncAttributeMaxDynamicSharedMemorySize, 65536);
    cudaFuncSetAttribute(select_kernel, cudaFuncAttributeMaxDynamicSharedMemorySize, 98304);
    cudaFuncSetAttribute(nms_kernel,    cudaFuncAttributeMaxDynamicSharedMemorySize, 24576);
    cudaFuncSetAttribute(merge_kernel,  cudaFuncAttributeMaxDynamicSharedMemorySize, 32768);

    amax_kernel<<<dim3((VECTOT + 255) / 256, 3, BATCH), 256>>>(m0, m1, m2);
    thr_kernel<<<BATCH, 1024>>>();
    thrw_kernel<<<(BATCH * 3 * NLOCP + 511) / 512, 512>>>();
    cand_kernel<<<dim3((NLOC + 511) / 512, 3, BATCH), 512, 65536>>>(m0, m1, m2);
    select_kernel<<<BATCH, 1024, 98304>>>(m0, m1, m2);
    nms_kernel<<<dim3(80, BATCH), 32, 24576>>>();
    merge_kernel<<<BATCH, 1024, 32768>>>(out, out_size);
}

// round 17
// speedup vs baseline: 1.0779x; 1.0779x over previous
#include <cuda_runtime.h>
#include <math.h>

#define BATCH   16
#define NLOC    7581
#define NLOCP   7584
#define TOPK    4096
#define CAP2    262144
#define MAXDET  100
#define NBINS   8192
#define FBINS   4096
#define VECTOT  1896
#define U64MAX  0xFFFFFFFFFFFFFFFFull
#define KEYMAX  0xBF800000u
#define NEG_INF __int_as_float(0xff800000)

__device__ float              g_objs[BATCH * 3 * NLOCP];
__device__ float              g_thr [BATCH * 3 * NLOCP];
__device__ unsigned int       g_hist[BATCH * NBINS];
__device__ unsigned int       g_lbkey[BATCH];
__device__ int                g_shift[BATCH];
__device__ int                g_cnt[BATCH];
__device__ unsigned long long g_cand[(size_t)BATCH * CAP2];
__device__ unsigned long long g_comp[BATCH * TOPK];
__device__ float4             g_box [BATCH * TOPK];
__device__ int                g_clsidx[BATCH * TOPK];
__device__ int                g_coffs[BATCH * 81];
__device__ float              g_ob[BATCH];

__constant__ int   c_lbp[3] = {0, 364, 1808};
__constant__ int   c_HW[3]  = {361, 1444, 5776};
__constant__ int   c_W[3]   = {19, 38, 76};
__constant__ int   c_nb[3]  = {0, 1083, 5415};
__constant__ float c_str[3] = {32.f, 16.f, 8.f};
__constant__ float c_bw2[9] = {58.f, 78.f, 186.5f,  15.f, 31.f, 29.5f,  5.f, 8.f, 16.5f};
__constant__ float c_bh2[9] = {45.f, 99.f, 163.f,   30.5f, 22.5f, 59.5f, 6.5f, 15.f, 11.5f};

__device__ __forceinline__ float sigm(float x) { return 1.f / (1.f + expf(-x)); }

__device__ __forceinline__ void vecmap(int vec, int& m, int& vbase, int& HW) {
    if (vec < 91)       { m = 0; vbase = 0;   HW = 361;  }
    else if (vec < 452) { m = 1; vbase = 91;  HW = 1444; }
    else                { m = 2; vbase = 452; HW = 5776; }
}

// warp-aggregated histogram add (merge only)
__device__ __forceinline__ void hadd(unsigned int* hist, int bin, bool active) {
    unsigned int amask = __ballot_sync(0xffffffffu, active);
    if (active) {
        unsigned int peers = __match_any_sync(amask, bin);
        int leader = __ffs(peers) - 1;
        if ((threadIdx.x & 31) == leader)
            atomicAdd(&hist[bin], (unsigned int)__popc(peers));
    }
}

// ---------------- fused objectness + per-anchor max-class histogram ----------------
__global__ __launch_bounds__(256) void amax_kernel(const float* __restrict__ m0,
                                                   const float* __restrict__ m1,
                                                   const float* __restrict__ m2) {
    __shared__ unsigned int sh[NBINS];
    int tid = threadIdx.x;
    for (int i = tid; i < NBINS; i += 256) sh[i] = 0u;
    __syncthreads();
    int b = blockIdx.z, a = blockIdx.y;
    int vec = blockIdx.x * 256 + tid;
    if (vec < VECTOT) {
        int m, vbase, HW; vecmap(vec, m, vbase, HW);
        int locm = (vec - vbase) * 4;
        int nv = HW - locm; if (nv > 4) nv = 4;
        const float* mp = (m == 0) ? m0 : ((m == 1) ? m1 : m2);
        const float* ch0 = mp + ((size_t)(b * 255 + a * 85)) * (size_t)HW;
        float cm0 = -1e30f, cm1 = -1e30f, cm2 = -1e30f, cm3 = -1e30f;
        float o0 = 0.f, o1 = 0.f, o2 = 0.f, o3 = 0.f;
        if (m > 0) {
            const float* cls = ch0 + (size_t)5 * HW + locm;
#pragma unroll 10
            for (int ch = 0; ch < 80; ++ch) {
                float4 v = __ldg((const float4*)(cls + (size_t)ch * HW));
                cm0 = fmaxf(cm0, v.x); cm1 = fmaxf(cm1, v.y);
                cm2 = fmaxf(cm2, v.z); cm3 = fmaxf(cm3, v.w);
            }
            float4 ov = __ldg((const float4*)(ch0 + (size_t)4 * HW + locm));
            o0 = ov.x; o1 = ov.y; o2 = ov.z; o3 = ov.w;
        } else {
            const float* cls = ch0 + (size_t)5 * HW + locm;
            for (int ch = 0; ch < 80; ++ch) {
                const float* r = cls + (size_t)ch * HW;
                cm0 = fmaxf(cm0, r[0]);
                if (nv > 1) cm1 = fmaxf(cm1, r[1]);
                if (nv > 2) cm2 = fmaxf(cm2, r[2]);
                if (nv > 3) cm3 = fmaxf(cm3, r[3]);
            }
            const float* orow = ch0 + (size_t)4 * HW + locm;
            o0 = orow[0];
            if (nv > 1) o1 = orow[1];
            if (nv > 2) o2 = orow[2];
            if (nv > 3) o3 = orow[3];
        }
        float cmv[4] = {cm0, cm1, cm2, cm3};
        float tov[4] = {o0, o1, o2, o3};
        int obase = (b * 3 + a) * NLOCP + c_lbp[m] + locm;
#pragma unroll
        for (int e = 0; e < 4; e++) {
            if (e < nv) {
                float obj = sigm(tov[e]);
                g_objs[obase + e] = obj;
                float cs = sigm(cmv[e]);
                unsigned int key = (obj >= 0.005f && cs > 0.05f)
                                       ? (__float_as_uint(cs * obj) | 0x80000000u) : 0u;
                atomicAdd(&sh[key >> 19], 1u);
            }
        }
    }
    __syncthreads();
    for (int i = tid; i < NBINS; i += 256) {
        unsigned int v = sh[i];
        if (v) atomicAdd(&g_hist[b * NBINS + i], v);
    }
}

// ---- top-down bin finders (1024 thr) ----
__device__ __forceinline__ void find_bin8(const unsigned int* hist, int K,
                                          int* part, int* wsum,
                                          int* out_bin, int* out_above) {
    int tid = threadIdx.x;
    int s = 0;
#pragma unroll
    for (int k = 0; k < 8; k++) s += (int)hist[tid * 8 + k];
    part[tid] = s;
    int v = s;
    for (int o = 16; o; o >>= 1) v += __shfl_xor_sync(0xffffffffu, v, o);
    if ((tid & 31) == 0) wsum[tid >> 5] = v;
    __syncthreads();
    if (tid == 0) {
        int cum = 0, bin = 0, wi;
        for (wi = 31; wi >= 0; --wi) {
            if (cum + wsum[wi] >= K) break;
            cum += wsum[wi];
        }
        if (wi >= 0) {
            int p;
            for (p = wi * 32 + 31; p > wi * 32; --p) {
                if (cum + part[p] >= K) break;
                cum += part[p];
            }
            int bb;
            for (bb = p * 8 + 7; bb > p * 8; --bb) {
                if (cum + (int)hist[bb] >= K) break;
                cum += (int)hist[bb];
            }
            bin = bb;
        }
        *out_bin = bin; *out_above = cum;
    }
    __syncthreads();
}

__device__ __forceinline__ void find_bin4(const unsigned int* hist, int K,
                                          int* part, int* wsum,
                                          int* out_bin, int* out_above) {
    int tid = threadIdx.x;
    int s = 0;
#pragma unroll
    for (int k = 0; k < 4; k++) s += (int)hist[tid * 4 + k];
    part[tid] = s;
    int v = s;
    for (int o = 16; o; o >>= 1) v += __shfl_xor_sync(0xffffffffu, v, o);
    if ((tid & 31) == 0) wsum[tid >> 5] = v;
    __syncthreads();
    if (tid == 0) {
        int cum = 0, bin = 0, wi;
        for (wi = 31; wi >= 0; --wi) {
            if (cum + wsum[wi] >= K) break;
            cum += wsum[wi];
        }
        if (wi >= 0) {
            int p;
            for (p = wi * 32 + 31; p > wi * 32; --p) {
                if (cum + part[p] >= K) break;
                cum += part[p];
            }
            int bb;
            for (bb = p * 4 + 3; bb > p * 4; --bb) {
                if (cum + (int)hist[bb] >= K) break;
                cum += (int)hist[bb];
            }
            bin = bb;
        }
        *out_bin = bin; *out_above = cum;
    }
    __syncthreads();
}

__device__ __forceinline__ void sel2048(const unsigned int* hist, int K, int top,
                                        int* part, int* wsum,
                                        int* out_bin, int* out_side) {
    int tid = threadIdx.x;
    int s = (int)hist[2 * tid] + (int)hist[2 * tid + 1];
    part[tid] = s;
    int v = s;
    for (int o = 16; o; o >>= 1) v += __shfl_xor_sync(0xffffffffu, v, o);
    if ((tid & 31) == 0) wsum[tid >> 5] = v;
    __syncthreads();
    if (tid == 0) {
        int cum = 0, bin;
        if (top) {
            int wi;
            for (wi = 31; wi > 0; --wi) {
                if (cum + wsum[wi] >= K) break;
                cum += wsum[wi];
            }
            int p;
            for (p = wi * 32 + 31; p > wi * 32; --p) {
                if (cum + part[p] >= K) break;
                cum += part[p];
            }
            int bb;
            for (bb = 2 * p + 1; bb > 2 * p; --bb) {
                if (cum + (int)hist[bb] >= K) break;
                cum += (int)hist[bb];
            }
            bin = bb;
        } else {
            int wi;
            for (wi = 0; wi < 31; ++wi) {
                if (cum + wsum[wi] >= K) break;
                cum += wsum[wi];
            }
            int p;
            for (p = wi * 32; p < wi * 32 + 31; ++p) {
                if (cum + part[p] >= K) break;
                cum += part[p];
            }
            int bb;
            for (bb = 2 * p; bb < 2 * p + 1; ++bb) {
                if (cum + (int)hist[bb] >= K) break;
                cum += (int)hist[bb];
            }
            bin = bb;
        }
        *out_bin = bin; *out_side = cum;
    }
    __syncthreads();
}

// ---------------- LB + fine shift (narrow) ----------------
__global__ __launch_bounds__(1024) void thr_kernel() {
    __shared__ unsigned int h[NBINS];
    __shared__ int part[1024];
    __shared__ int wsum[32];
    __shared__ int sbin, sabove;
    int b = blockIdx.x, tid = threadIdx.x;
    for (int i = tid; i < NBINS; i += 1024) {
        h[i] = g_hist[b * NBINS + i];
        g_hist[b * NBINS + i] = 0u;
    }
    __syncthreads();
    find_bin8(h, TOPK, part, wsum, &sbin, &sabove);
    if (tid == 0) {
        unsigned int lbkey = ((unsigned int)sbin) << 19;
        g_lbkey[b] = lbkey;
        unsigned int R = KEYMAX - lbkey;
        int sh = 0;
        while ((R >> sh) > (unsigned)(FBINS - 1)) sh++;
        g_shift[b] = sh;
    }
}

// ---------------- per-anchor raw-logit thresholds (wide) ----------------
__global__ __launch_bounds__(512) void thrw_kernel() {
    int t = blockIdx.x * 512 + threadIdx.x;
    if (t >= BATCH * 3 * NLOCP) return;
    int b = t / (3 * NLOCP);
    float LB = __uint_as_float(g_lbkey[b] & 0x7FFFFFFFu);
    float obj = g_objs[t];
    float thr;
    if (obj < 0.005f) thr = 3.0e38f;
    else if (LB <= 0.f) thr = -2.9446f;
    else {
        float ratio = LB / obj;
        if (ratio >= 1.0f) thr = 3.0e38f;
        else thr = fmaxf(logf(ratio / (1.0f - ratio)) - 1e-2f, -2.9446f);
    }
    g_thr[t] = thr;
}

// ------- candidate generation (R14 class-major float4) + fine histogram -------
__global__ __launch_bounds__(512) void cand_kernel(const float* __restrict__ m0,
                                                   const float* __restrict__ m1,
                                                   const float* __restrict__ m2) {
    extern __shared__ char cms[];
    unsigned long long* sbuf = (unsigned long long*)cms;          // 32 KB [4096]
    unsigned int* shist = (unsigned int*)(cms + 32768);           // 16 KB [4096]
    __shared__ int scnt;
    __shared__ int sbase;
    int b = blockIdx.z;
    int ac = blockIdx.y;
    int a = ac / 80, cl = ac - a * 80;
    int tid = threadIdx.x;
    if (tid == 0) scnt = 0;
    for (int i = tid; i < FBINS; i += 512) shist[i] = 0u;
    __syncthreads();
    unsigned int lbk = g_lbkey[b];
    int shiftv = g_shift[b];

#pragma unroll
    for (int half = 0; half < 2; half++) {
        int vec = blockIdx.x * 1024 + half * 512 + tid;
        if (vec < VECTOT) {
            int m, vbase, HW; vecmap(vec, m, vbase, HW);
            int locm = (vec - vbase) * 4;
            int nv = HW - locm; if (nv > 4) nv = 4;
            const float* mp = (m == 0) ? m0 : ((m == 1) ? m1 : m2);
            const float* cr = mp + ((size_t)(b * 255 + a * 85 + 5 + cl)) * (size_t)HW + locm;
            int pbase = (b * 3 + a) * NLOCP + c_lbp[m] + locm;
            float4 tv = *(const float4*)(g_thr + pbase);
            float cva[4], tva[4] = {tv.x, tv.y, tv.z, tv.w};
            if (m > 0) {
                float4 c4 = __ldg((const float4*)cr);
                cva[0] = c4.x; cva[1] = c4.y; cva[2] = c4.z; cva[3] = c4.w;
            } else {
                cva[0] = cr[0];
                cva[1] = (nv > 1) ? cr[1] : -1e30f;
                cva[2] = (nv > 2) ? cr[2] : -1e30f;
                cva[3] = (nv > 3) ? cr[3] : -1e30f;
            }
#pragma unroll
            for (int e = 0; e < 4; e++) {
                if (e < nv && cva[e] >= tva[e]) {
                    float obj = g_objs[pbase + e];
                    float cs = sigm(cva[e]);
                    if (cs > 0.05f && obj >= 0.005f) {
                        unsigned int key = __float_as_uint(cs * obj) | 0x80000000u;
                        if (key >= lbk) {
                            int nI = c_nb[m] + (locm + e) * 3 + a;
                            unsigned int idx = (unsigned int)nI * 80u + (unsigned int)cl;
                            int p = atomicAdd(&scnt, 1);
                            sbuf[p] = (((unsigned long long)(~key)) << 32)
                                      | (unsigned long long)idx;
                            atomicAdd(&shist[(key - lbk) >> shiftv], 1u);
                        }
                    }
                }
            }
        }
    }
    __syncthreads();
    int c = scnt;
    if (c > 0) {
        if (tid == 0) sbase = atomicAdd(&g_cnt[b], c);
        __syncthreads();
        int gb = sbase;
        for (int i = tid; i < c; i += 512) {
            int pos = gb + i;
            if (pos < CAP2) g_cand[(size_t)b * CAP2 + pos] = sbuf[i];
        }
    }
    for (int i = tid; i < FBINS; i += 512) {
        unsigned int v = shist[i];
        if (v) atomicAdd(&g_hist[b * NBINS + i], v);
    }
}

// ------- select: fine T2 + filtered load + exact cascade + decode + segmentation -------
__global__ __launch_bounds__(1024) void select_kernel(const float* __restrict__ m0,
                                                      const float* __restrict__ m1,
                                                      const float* __restrict__ m2) {
    extern __shared__ char smraw[];
    unsigned long long* comp2 = (unsigned long long*)smraw;          // 64 KB [8192]
    unsigned long long* comp = (unsigned long long*)(smraw + 65536); // 32 KB [4096]
    unsigned int* fineh = (unsigned int*)smraw;                      // overlaps comp2
    __shared__ unsigned int hist[2048];
    __shared__ int part[1024];
    __shared__ int wsum[32];
    __shared__ int sn, sb1, sa1, sb2, sa2, sb3, sa3, scnteq, sib1, sbl1, sib2, sdum;
    __shared__ int sfbin, sfdum;
    __shared__ int scc, scc2;
    __shared__ float wred[32];
    __shared__ int ccount[80];
    __shared__ int coffs[81];
    __shared__ int ccur[80];

    int b = blockIdx.x, tid = threadIdx.x;
    if (tid == 0) {
        int nn = g_cnt[b]; if (nn > CAP2) nn = CAP2;
        sn = nn; g_cnt[b] = 0;
        scc = 0;
    }
    if (tid < 80) { ccount[tid] = 0; ccur[tid] = 0; }
    __syncthreads();
    int n = sn;
    const unsigned long long* cand = g_cand + (size_t)b * CAP2;

    for (int i = tid; i < FBINS; i += 1024) {
        fineh[i] = g_hist[b * NBINS + i];
        g_hist[b * NBINS + i] = 0u;
    }
    __syncthreads();
    find_bin4(fineh, TOPK, part, wsum, &sfbin, &sfdum);
    unsigned int T2 = g_lbkey[b] + (((unsigned int)sfbin) << g_shift[b]);
    __syncthreads();

    for (int i = tid; i < n; i += 1024) {
        unsigned long long e = cand[i];
        unsigned int key = ~(unsigned int)(e >> 32);
        if (key >= T2) {
            int p = atomicAdd(&scc, 1);
            if (p < 8192) comp2[p] = e;
        }
    }
    __syncthreads();
    int m = scc; if (m > 8192) m = 8192;

    unsigned int T = 0u; int tie_sel = 0; unsigned int Istar = 0u;
    if (m > TOPK) {
        for (int i = tid; i < 2048; i += 1024) hist[i] = 0u;
        __syncthreads();
        for (int i = tid; i < m; i += 1024) {
            unsigned int key = ~(unsigned int)(comp2[i] >> 32);
            atomicAdd(&hist[key >> 21], 1u);
        }
        __syncthreads();
        sel2048(hist, TOPK, 1, part, wsum, &sb1, &sa1);
        int b1 = sb1, K2 = TOPK - sa1;
        __syncthreads();
        for (int i = tid; i < 2048; i += 1024) hist[i] = 0u;
        __syncthreads();
        for (int i = tid; i < m; i += 1024) {
            unsigned int key = ~(unsigned int)(comp2[i] >> 32);
            if ((int)(key >> 21) == b1) atomicAdd(&hist[(key >> 10) & 0x7FFu], 1u);
        }
        __syncthreads();
        sel2048(hist, K2, 1, part, wsum, &sb2, &sa2);
        int b2 = sb2, K3 = K2 - sa2;
        unsigned int pre = ((unsigned int)b1 << 11) | (unsigned int)b2;
        __syncthreads();
        for (int i = tid; i < 2048; i += 1024) hist[i] = 0u;
        __syncthreads();
        for (int i = tid; i < m; i += 1024) {
            unsigned int key = ~(unsigned int)(comp2[i] >> 32);
            if ((key >> 10) == pre) atomicAdd(&hist[key & 0x3FFu], 1u);
        }
        __syncthreads();
        sel2048(hist, K3, 1, part, wsum, &sb3, &sa3);
        if (tid == 0) scnteq = (int)hist[sb3];
        __syncthreads();
        T = (pre << 10) | (unsigned int)sb3;
        int need_eq = K3 - sa3;
        if (scnteq > need_eq) {
            tie_sel = 1;
            __syncthreads();
            for (int i = tid; i < 2048; i += 1024) hist[i] = 0u;
            __syncthreads();
            for (int i = tid; i < m; i += 1024) {
                unsigned long long e = comp2[i];
                unsigned int key = ~(unsigned int)(e >> 32);
                if (key == T) atomicAdd(&hist[((unsigned int)e) >> 11], 1u);
            }
            __syncthreads();
            sel2048(hist, need_eq, 0, part, wsum, &sib1, &sbl1);
            int ib1 = sib1, Kr = need_eq - sbl1;
            __syncthreads();
            for (int i = tid; i < 2048; i += 1024) hist[i] = 0u;
            __syncthreads();
            for (int i = tid; i < m; i += 1024) {
                unsigned long long e = comp2[i];
                unsigned int key = ~(unsigned int)(e >> 32);
                unsigned int idx = (unsigned int)e;
                if (key == T && (int)(idx >> 11) == ib1)
                    atomicAdd(&hist[idx & 0x7FFu], 1u);
            }
            __syncthreads();
            sel2048(hist, Kr, 0, part, wsum, &sib2, &sdum);
            Istar = (((unsigned int)sib1) << 11) | (unsigned int)sib2;
        }
    }
    if (tid == 0) scc2 = 0;
    __syncthreads();

    float lmax = NEG_INF;
    for (int i = tid; i < m; i += 1024) {
        unsigned long long e = comp2[i];
        unsigned int key = ~(unsigned int)(e >> 32);
        unsigned int idx = (unsigned int)e;
        bool keep;
        if (m <= TOPK) keep = true;
        else keep = (key > T) || (key == T && (!tie_sel || idx <= Istar));
        if (keep) {
            int slot = atomicAdd(&scc2, 1);
            int nI = (int)(idx / 80u);
            int mm = (nI < 1083) ? 0 : ((nI < 5415) ? 1 : 2);
            int rem = nI - c_nb[mm];
            int locm = rem / 3, a = rem - locm * 3;
            const float* mp = (mm == 0) ? m0 : ((mm == 1) ? m1 : m2);
            size_t HW = (size_t)c_HW[mm];
            const float* bp = mp + ((size_t)b * 255 + a * 85) * HW + locm;
            float tx = bp[0], ty = bp[HW], tw = bp[2 * HW], th = bp[3 * HW];
            float s = c_str[mm]; int W = c_W[mm];
            int hh = locm / W, ww = locm - hh * W;
            float sx = sigm(tx), sy = sigm(ty);
            float cx = (float)ww * s + 0.5f * s + (sx - 0.5f) * s;
            float cy = (float)hh * s + 0.5f * s + (sy - 0.5f) * s;
            float wx = c_bw2[mm * 3 + a] * expf(tw);
            float wy = c_bh2[mm * 3 + a] * expf(th);
            float4 bx = make_float4(cx - wx, cy - wy, cx + wx, cy + wy);
            comp[slot] = e;
            g_comp[b * TOPK + slot] = e;
            g_box[b * TOPK + slot] = bx;
            lmax = fmaxf(lmax, fmaxf(fmaxf(bx.x, bx.y), fmaxf(bx.z, bx.w)));
        }
    }
    __syncthreads();
    int kept = scc2;
    for (int i = tid; i < TOPK; i += 1024) {
        if (i >= kept) { comp[i] = U64MAX; g_comp[b * TOPK + i] = U64MAX; }
    }
    lmax = fmaxf(lmax, 0.f);
    for (int o = 16; o; o >>= 1) lmax = fmaxf(lmax, __shfl_xor_sync(0xffffffffu, lmax, o));
    if ((tid & 31) == 0) wred[tid >> 5] = lmax;
    __syncthreads();
    if (tid < 32) {
        float v = wred[tid];
        for (int o = 16; o; o >>= 1) v = fmaxf(v, __shfl_xor_sync(0xffffffffu, v, o));
        if (tid == 0) g_ob[b] = v + 1.0f;
    }
    __syncthreads();

    for (int i = tid; i < TOPK; i += 1024) {
        unsigned long long e = comp[i];
        if (e != U64MAX) atomicAdd((unsigned int*)&ccount[(unsigned int)e % 80u], 1u);
    }
    __syncthreads();
    if (tid == 0) {
        int acc = 0;
        for (int c = 0; c < 80; c++) { coffs[c] = acc; acc += ccount[c]; }
        coffs[80] = acc;
    }
    __syncthreads();
    if (tid < 81) g_coffs[b * 81 + tid] = coffs[tid];
    for (int i = tid; i < TOPK; i += 1024) {
        unsigned long long e = comp[i];
        if (e != U64MAX) {
            int lbl = (int)((unsigned int)e % 80u);
            int p = coffs[lbl] + atomicAdd(&ccur[lbl], 1);
            g_clsidx[b * TOPK + p] = i;
        }
    }
}

// ------- per-class greedy NMS: one warp-block per (class, image), 24 KB smem -------
__global__ __launch_bounds__(32) void nms_kernel() {
    extern __shared__ char nsm[];
    unsigned long long* lcomp = (unsigned long long*)nsm;       // 2 KB [256]
    float4* lbox = (float4*)(nsm + 2048);                       // 4 KB [256]
    int* gslot = (int*)(nsm + 6144);                            // 1 KB [256]
    int* lidx = (int*)(nsm + 7168);                             // 16 KB [4096]

    int c = blockIdx.x, b = blockIdx.y;
    int lane = threadIdx.x;
    int s0 = g_coffs[b * 81 + c], e0 = g_coffs[b * 81 + c + 1];
    int k = e0 - s0;
    if (k <= 1) return;
    float oc = (float)c * g_ob[b];

    if (k <= 256) {
        for (int i = lane; i < k; i += 32) {
            int g = g_clsidx[b * TOPK + s0 + i];
            gslot[i] = g;
            lcomp[i] = g_comp[b * TOPK + g];
            lbox[i] = g_box[b * TOPK + g];
            lidx[i] = i;
        }
        __syncwarp();
        for (int pos = 0; pos < k; ++pos) {
            unsigned long long best = U64MAX; int bi = pos;
            for (int i = pos + lane; i < k; i += 32) {
                unsigned long long v = lcomp[lidx[i]];
                if (v < best) { best = v; bi = i; }
            }
            for (int o = 16; o; o >>= 1) {
                unsigned long long ov = __shfl_xor_sync(0xffffffffu, best, o);
                int oi = __shfl_xor_sync(0xffffffffu, bi, o);
                if (ov < best) { best = ov; bi = oi; }
            }
            if (lane == 0 && bi != pos) {
                int t = lidx[pos]; lidx[pos] = lidx[bi]; lidx[bi] = t;
            }
            __syncwarp();
            int slot = lidx[pos];
            float4 bc = lbox[slot];
            float cx0 = bc.x + oc, cy0 = bc.y + oc, cx1 = bc.z + oc, cy1 = bc.w + oc;
            float a2 = (cx1 - cx0) * (cy1 - cy0);
            bool sup = false;
            for (int j = lane; j < pos; j += 32) {
                int sj = lidx[j];
                if (lcomp[sj] != U64MAX) {
                    float4 bk = lbox[sj];
                    float kx0 = bk.x + oc, ky0 = bk.y + oc;
                    float kx1 = bk.z + oc, ky1 = bk.w + oc;
                    float tlx = fmaxf(kx0, cx0), tly = fmaxf(ky0, cy0);
                    float brx = fminf(kx1, cx1), bry = fminf(ky1, cy1);
                    float iw = fmaxf(brx - tlx, 0.f), ih = fmaxf(bry - tly, 0.f);
                    float inter = iw * ih;
                    float a1 = (kx1 - kx0) * (ky1 - ky0);
                    if (inter / (a1 + a2 - inter + 1e-12f) > 0.45f) sup = true;
                }
            }
            if (__any_sync(0xffffffffu, sup)) {
                if (lane == 0) lcomp[slot] = U64MAX;
            }
            __syncwarp();
        }
        for (int i = lane; i < k; i += 32)
            g_comp[b * TOPK + gslot[i]] = lcomp[i];
    } else {
        for (int i = lane; i < k; i += 32) lidx[i] = g_clsidx[b * TOPK + s0 + i];
        __syncwarp();
        for (int pos = 0; pos < k; ++pos) {
            unsigned long long best = U64MAX; int bi = pos;
            for (int i = pos + lane; i < k; i += 32) {
                unsigned long long v = g_comp[b * TOPK + lidx[i]];
                if (v < best) { best = v; bi = i; }
            }
            for (int o = 16; o; o >>= 1) {
                unsigned long long ov = __shfl_xor_sync(0xffffffffu, best, o);
                int oi = __shfl_xor_sync(0xffffffffu, bi, o);
                if (ov < best) { best = ov; bi = oi; }
            }
            if (lane == 0 && bi != pos) {
                int t = lidx[pos]; lidx[pos] = lidx[bi]; lidx[bi] = t;
            }
            __syncwarp();
            int slot = lidx[pos];
            float4 bc = g_box[b * TOPK + slot];
            float cx0 = bc.x + oc, cy0 = bc.y + oc, cx1 = bc.z + oc, cy1 = bc.w + oc;
            float a2 = (cx1 - cx0) * (cy1 - cy0);
            bool sup = false;
            for (int j = lane; j < pos; j += 32) {
                int sj = lidx[j];
                if (g_comp[b * TOPK + sj] != U64MAX) {
                    float4 bk = g_box[b * TOPK + sj];
                    float kx0 = bk.x + oc, ky0 = bk.y + oc;
                    float kx1 = bk.z + oc, ky1 = bk.w + oc;
                    float tlx = fmaxf(kx0, cx0), tly = fmaxf(ky0, cy0);
                    float brx = fminf(kx1, cx1), bry = fminf(ky1, cy1);
                    float iw = fmaxf(brx - tlx, 0.f), ih = fmaxf(bry - tly, 0.f);
                    float inter = iw * ih;
                    float a1 = (kx1 - kx0) * (ky1 - ky0);
                    if (inter / (a1 + a2 - inter + 1e-12f) > 0.45f) sup = true;
                }
            }
            if (__any_sync(0xffffffffu, sup)) {
                if (lane == 0) g_comp[b * TOPK + slot] = U64MAX;
            }
            __syncwarp();
        }
    }
}

// ------- merge: top-100 survivors by composite order -------
__global__ __launch_bounds__(1024) void merge_kernel(float* __restrict__ out, int out_size) {
    extern __shared__ char msm[];
    unsigned long long* comp = (unsigned long long*)msm;        // 32 KB [4096]
    __shared__ unsigned int hist[2048];
    __shared__ int part[1024];
    __shared__ int wsum[32];
    __shared__ int snsurv, souta;
    __shared__ int ssbin, ssbelow;
    __shared__ unsigned long long outc[128];
    __shared__ int outslot[128];

    int b = blockIdx.x, tid = threadIdx.x;
    int lane = tid & 31;
    if (tid == 0) { snsurv = 0; souta = 0; }
    __syncthreads();
    {
        int lc = 0;
#pragma unroll
        for (int k2 = 0; k2 < 4; k2++) {
            int i = k2 * 1024 + tid;
            unsigned long long v = g_comp[b * TOPK + i];
            comp[i] = v;
            if (v != U64MAX) lc++;
        }
        for (int o = 16; o; o >>= 1) lc += __shfl_xor_sync(0xffffffffu, lc, o);
        if (lane == 0 && lc) atomicAdd(&snsurv, lc);
    }
    __syncthreads();
    int nsurv = snsurv;
    unsigned long long Cstar = U64MAX;
    if (nsurv > MAXDET) {
        unsigned long long pref = 0ull; int prefbits = 0; int K = MAXDET;
        const int shifts[6]  = {53, 42, 31, 20, 9, 0};
        const int bitsarr[6] = {11, 11, 11, 11, 11, 9};
        for (int p = 0; p < 6; p++) {
            for (int i = tid; i < 2048; i += 1024) hist[i] = 0u;
            __syncthreads();
            unsigned long long msk = (1ull << bitsarr[p]) - 1ull;
#pragma unroll
            for (int k2 = 0; k2 < 4; k2++) {
                int i = k2 * 1024 + tid;
                unsigned long long v = comp[i];
                bool act = (v != U64MAX) &&
                           (prefbits == 0 || (v >> (64 - prefbits)) == pref);
                hadd(hist, act ? (int)((v >> shifts[p]) & msk) : 0, act);
            }
            __syncthreads();
            sel2048(hist, K, 0, part, wsum, &ssbin, &ssbelow);
            pref = (pref << bitsarr[p]) | (unsigned long long)ssbin;
            prefbits += bitsarr[p];
            K -= ssbelow;
            __syncthreads();
        }
        Cstar = pref;
    }
#pragma unroll
    for (int k2 = 0; k2 < 4; k2++) {
        int i = k2 * 1024 + tid;
        unsigned long long v = comp[i];
        if (v != U64MAX && v <= Cstar) {
            int p = atomicAdd(&souta, 1);
            if (p < 128) { outc[p] = v; outslot[p] = i; }
        }
    }
    __syncthreads();
    int nout = souta; if (nout > 128) nout = 128;
    if (tid < 128 && tid >= nout) { outc[tid] = U64MAX; outslot[tid] = 0; }
    __syncthreads();
    for (int k = 2; k <= 128; k <<= 1) {
        for (int j = k >> 1; j > 0; j >>= 1) {
            if (tid < 128) {
                int ix = tid ^ j;
                if (ix > tid) {
                    unsigned long long A = outc[tid], B = outc[ix];
                    bool up = ((tid & k) == 0);
                    if ((A > B) == up) {
                        outc[tid] = B; outc[ix] = A;
                        int t = outslot[tid]; outslot[tid] = outslot[ix]; outslot[ix] = t;
                    }
                }
            }
            __syncthreads();
        }
    }
    bool dets_only = (out_size <= BATCH * MAXDET * 5);
    if (tid < MAXDET) {
        unsigned long long e = outc[tid];
        float* o = out + (size_t)(b * MAXDET + tid) * 5;
        if (e != U64MAX) {
            float4 bx = g_box[b * TOPK + outslot[tid]];
            unsigned int key = ~(unsigned int)(e >> 32);
            o[0] = bx.x; o[1] = bx.y; o[2] = bx.z; o[3] = bx.w;
            o[4] = __uint_as_float(key & 0x7FFFFFFFu);
            if (!dets_only)
                out[BATCH * MAXDET * 5 + b * MAXDET + tid] =
                    (float)((unsigned int)e % 80u);
        } else {
            o[0] = 0.f; o[1] = 0.f; o[2] = 0.f; o[3] = 0.f; o[4] = 0.f;
            if (!dets_only) out[BATCH * MAXDET * 5 + b * MAXDET + tid] = -1.0f;
        }
    }
}

// ---------------- launcher ----------------
extern "C" void kernel_launch(void* const* d_in, const int* in_sizes, int n_in,
                              void* d_out, int out_size) {
    const float* m0 = (const float*)d_in[0];
    const float* m1 = (const float*)d_in[1];
    const float* m2 = (const float*)d_in[2];
    float* out = (float*)d_out;

    cudaFuncSetAttribute(cand_kernel,   cudaFuncAttributeMaxDynamicSharedMemorySize, 49152);
    cudaFuncSetAttribute(select_kernel, cudaFuncAttributeMaxDynamicSharedMemorySize, 98304);
    cudaFuncSetAttribute(nms_kernel,    cudaFuncAttributeMaxDynamicSharedMemorySize, 24576);
    cudaFuncSetAttribute(merge_kernel,  cudaFuncAttributeMaxDynamicSharedMemorySize, 32768);

    amax_kernel<<<dim3((VECTOT + 255) / 256, 3, BATCH), 256>>>(m0, m1, m2);
    thr_kernel<<<BATCH, 1024>>>();
    thrw_kernel<<<(BATCH * 3 * NLOCP + 511) / 512, 512>>>();
    cand_kernel<<<dim3(2, 240, BATCH), 512, 49152>>>(m0, m1, m2);
    select_kernel<<<BATCH, 1024, 98304>>>(m0, m1, m2);
    nms_kernel<<<dim3(80, BATCH), 32, 24576>>>();
    merge_kernel<<<BATCH, 1024, 32768>>>(out, out_size);
}